// round 15
// baseline (speedup 1.0000x reference)
#include <cuda_runtime.h>

// QConv1d, conjugation closed form; f32x2 lanes hold a T-PAIR (t, t+1),
// fed by a transposed (SoA) smem tile so packing needs ~no movs.
// One co per block (grid.y); 8 ci-warps x 2 sequential ci; smem reduction.
// x: (B, CIN, T, 4)   a,b,c: (COUT, CIN, FL)   out: (B, COUT, TOUT, 4)

#define B_    2
#define CIN_  16
#define COUT_ 16
#define T_    2048
#define FL_   9
#define TOUT_ 2040
#define GRP   8          // ci warps per block (each does ci = g and g+8)
#define TT    64         // t per block (32 lanes x t-pair)
#define TS    72         // staged t extent (TT + FL - 1)

typedef unsigned long long ull;

struct __align__(16) ull2x { ull a, b; };

__device__ __forceinline__ ull pk2(float lo, float hi) {
    ull r; asm("mov.b64 %0,{%1,%2};" : "=l"(r)
               : "r"(__float_as_uint(lo)), "r"(__float_as_uint(hi)));
    return r;
}
__device__ __forceinline__ void upk2(ull v, float& lo, float& hi) {
    unsigned a, b; asm("mov.b64 {%0,%1},%2;" : "=r"(a), "=r"(b) : "l"(v));
    lo = __uint_as_float(a); hi = __uint_as_float(b);
}
__device__ __forceinline__ ull bc2(float v) { return pk2(v, v); }
__device__ __forceinline__ ull f2(ull a, ull b, ull c) {
    ull r; asm("fma.rn.f32x2 %0,%1,%2,%3;" : "=l"(r) : "l"(a), "l"(b), "l"(c));
    return r;
}
__device__ __forceinline__ ull m2(ull a, ull b) {
    ull r; asm("mul.rn.f32x2 %0,%1,%2;" : "=l"(r) : "l"(a), "l"(b));
    return r;
}
__device__ __forceinline__ ull a2_(ull a, ull b) {
    ull r; asm("add.rn.f32x2 %0,%1,%2;" : "=l"(r) : "l"(a), "l"(b));
    return r;
}
__device__ __forceinline__ float rcpf(float x) {
    float r; asm("rcp.approx.f32 %0,%1;" : "=f"(r) : "f"(x));
    return r;
}
// (hi(A), lo(B)) -> packed: the sliding-window odd-tap pair
__device__ __forceinline__ ull mixp(ull A, ull B) {
    float al, ah, bl, bh; upk2(A, al, ah); upk2(B, bl, bh);
    return pk2(ah, bl);
}

__global__ __launch_bounds__(32 * GRP)
void qconv1d_kernel(const float* __restrict__ x,
                    const float* __restrict__ pa,
                    const float* __restrict__ pb,
                    const float* __restrict__ pc,
                    float* __restrict__ out)
{
    __shared__ float xs[4][CIN_][TS];         // transposed tile: [comp][ci][t]
    __shared__ ull2x spAB[CIN_][FL_];         // {bc2(a), bc2(b)} for this co
    __shared__ ull   spC[CIN_][FL_];          // bc2(c)
    __shared__ ull   red[GRP - 1][32][4];

    const int tx    = threadIdx.x;            // lane: owns t-pair (t0, t0+1)
    const int g     = threadIdx.y;            // ci warp group
    const int tid   = g * 32 + tx;
    const int tbase = blockIdx.x * TT;
    const int co    = blockIdx.y;
    const int b     = blockIdx.z;
    const int t0    = tbase + 2 * tx;

    // ---- stage x tile transposed (SoA) ----
    {
        const float4* x4 = reinterpret_cast<const float4*>(x) + (size_t)b * CIN_ * T_;
        for (int idx = tid; idx < CIN_ * TS; idx += 32 * GRP) {
            const int cis = idx / TS;
            const int tt  = idx % TS;
            int gt = tbase + tt; if (gt > T_ - 1) gt = T_ - 1;
            const float4 v = __ldg(&x4[(size_t)cis * T_ + gt]);
            xs[0][cis][tt] = v.x;
            xs[1][cis][tt] = v.y;
            xs[2][cis][tt] = v.z;
            xs[3][cis][tt] = v.w;
        }
        // params for this co, pre-broadcast into packed form
        if (tid < CIN_ * FL_) {
            const int cci = tid / FL_, f = tid % FL_;
            const int s = (co * CIN_ + cci) * FL_ + f;
            ull2x ab;
            ab.a = bc2(__ldg(pa + s));
            ab.b = bc2(__ldg(pb + s));
            spAB[cci][f] = ab;
            spC[cci][f]  = bc2(__ldg(pc + s));
        }
    }
    __syncthreads();

    ull aw = 0, ax = 0, ay = 0, az = 0;       // positive accumulators (packed t-pair)
    ull Sn = 0, nx = 0, ny = 0, nz = 0;       // sign-split negatives
    const ull NEG1 = bc2(-1.0f);

    #pragma unroll
    for (int cc = 0; cc < 2; ++cc) {
        const int ci = g + cc * GRP;
        const ull* row0 = reinterpret_cast<const ull*>(xs[0][ci]);
        const ull* row1 = reinterpret_cast<const ull*>(xs[1][ci]);
        const ull* row2 = reinterpret_cast<const ull*>(xs[2][ci]);
        const ull* row3 = reinterpret_cast<const ull*>(xs[3][ci]);

        // center tap qp (pair index lane+2 == tap f=4), packed over the t-pair
        const ull pw2 = row0[tx + 2];
        const ull vx2 = row1[tx + 2];
        const ull vy2 = row2[tx + 2];
        const ull vz2 = row3[tx + 2];
        const ull nvx2 = m2(vx2, NEG1);
        const ull nvy2 = m2(vy2, NEG1);
        const ull nvz2 = m2(vz2, NEG1);
        const ull vsq2  = f2(vx2, vx2, f2(vy2, vy2, m2(vz2, vz2)));
        const ull nvsq2 = m2(vsq2, NEG1);

        // sliding window of aligned pairs per component
        ull c0 = row0[tx], c1 = row1[tx], c2 = row2[tx], c3 = row3[tx];

        #pragma unroll
        for (int k = 0; k < 5; ++k) {
            // ---- even tap f = 2k : u2 = current aligned pairs ----
            #pragma unroll
            for (int half = 0; half < 2; ++half) {
                const int f = 2 * k + half;
                if (f >= FL_) break;
                ull s2, ux2, uy2, uz2;
                ull n0, n1, n2, n3;
                if (half == 0) {
                    s2 = c0; ux2 = c1; uy2 = c2; uz2 = c3;
                } else {
                    n0 = row0[tx + k + 1]; n1 = row1[tx + k + 1];
                    n2 = row2[tx + k + 1]; n3 = row3[tx + k + 1];
                    s2  = mixp(c0, n0); ux2 = mixp(c1, n1);
                    uy2 = mixp(c2, n2); uz2 = mixp(c3, n3);
                    c0 = n0; c1 = n1; c2 = n2; c3 = n3;
                }

                // packed invariants: R(w) = w^2 u + w*(2 v x u) + (2(v.u) v - vsq u)
                ull dp = f2(vx2, ux2, f2(vy2, uy2, m2(vz2, uz2)));
                const ull dd2 = a2_(dp, dp);
                ull crx = f2(vy2, uz2, m2(nvz2, uy2)); crx = a2_(crx, crx);
                ull cry = f2(vz2, ux2, m2(nvx2, uz2)); cry = a2_(cry, cry);
                ull crz = f2(vx2, uy2, m2(nvy2, ux2)); crz = a2_(crz, crz);
                const ull a0x = f2(dd2, vx2, m2(nvsq2, ux2));
                const ull a0y = f2(dd2, vy2, m2(nvsq2, uy2));
                const ull a0z = f2(dd2, vz2, m2(nvsq2, uz2));

                const ull2x AB = spAB[ci][f];
                const ull C2 = spC[ci][f];

                const ull w2   = a2_(pw2, C2);
                const ull nsq2 = f2(w2, w2, vsq2);
                float nlo, nhi; upk2(nsq2, nlo, nhi);
                const ull rn2  = pk2(rcpf(nlo), rcpf(nhi));
                const ull arn2 = m2(AB.a, rn2);

                const ull Rx = m2(f2(w2, f2(w2, ux2, crx), a0x), arn2);
                const ull Ry = m2(f2(w2, f2(w2, uy2, cry), a0y), arn2);
                const ull Rz = m2(f2(w2, f2(w2, uz2, crz), a0z), arn2);
                const ull Rw = m2(s2, AB.a);
                const ull qw2 = a2_(s2, AB.b);

                // acc += (q + b e) (x) R  — negatives collected separately
                aw = f2(qw2, Rw, aw);
                Sn = f2(ux2, Rx, Sn);
                Sn = f2(uy2, Ry, Sn);
                Sn = f2(uz2, Rz, Sn);
                ax = f2(qw2, Rx, ax);
                ax = f2(ux2, Rw, ax);
                ax = f2(uy2, Rz, ax);
                nx = f2(uz2, Ry, nx);
                ay = f2(qw2, Ry, ay);
                ny = f2(ux2, Rz, ny);
                ay = f2(uy2, Rw, ay);
                ay = f2(uz2, Rx, ay);
                az = f2(qw2, Rz, az);
                az = f2(ux2, Ry, az);
                nz = f2(uy2, Rx, nz);
                az = f2(uz2, Rw, az);
            }
        }
    }

    // fold negatives once
    aw = f2(Sn, NEG1, aw);
    ax = f2(nx, NEG1, ax);
    ay = f2(ny, NEG1, ay);
    az = f2(nz, NEG1, az);

    // flat reduction over the 8 ci warps (packed adds)
    if (g > 0) {
        red[g - 1][tx][0] = aw;
        red[g - 1][tx][1] = ax;
        red[g - 1][tx][2] = ay;
        red[g - 1][tx][3] = az;
    }
    __syncthreads();
    if (g == 0 && t0 < TOUT_) {
        #pragma unroll
        for (int k = 0; k < GRP - 1; ++k) {
            aw = a2_(aw, red[k][tx][0]);
            ax = a2_(ax, red[k][tx][1]);
            ay = a2_(ay, red[k][tx][2]);
            az = a2_(az, red[k][tx][3]);
        }
        float w0, w1, x0, x1, y0, y1, z0, z1;
        upk2(aw, w0, w1); upk2(ax, x0, x1); upk2(ay, y0, y1); upk2(az, z0, z1);
        float4* o4 = reinterpret_cast<float4*>(out)
                   + ((size_t)b * COUT_ + co) * TOUT_;
        o4[t0]     = make_float4(w0, x0, y0, z0);   // t0 < 2040 (even) implies
        o4[t0 + 1] = make_float4(w1, x1, y1, z1);   // t0+1 <= 2039 as well
    }
}

extern "C" void kernel_launch(void* const* d_in, const int* in_sizes, int n_in,
                              void* d_out, int out_size)
{
    const float* x  = (const float*)d_in[0];
    const float* pa = (const float*)d_in[1];
    const float* pb = (const float*)d_in[2];
    const float* pc = (const float*)d_in[3];
    float* out = (float*)d_out;

    dim3 block(32, GRP, 1);
    dim3 grid((TOUT_ + TT - 1) / TT, COUT_, B_);   // 32 x 16 x 2 = 1024 blocks
    qconv1d_kernel<<<grid, block>>>(x, pa, pb, pc, out);
}

// round 16
// speedup vs baseline: 1.1780x; 1.1780x over previous
#include <cuda_runtime.h>

// QConv1d, conjugation closed form — SCALAR twin of the R13 packed kernel.
// NQ=2 co per thread, all math improvements, no f32x2 (tests FFMA2 issue cost).
// x: (B, CIN, T, 4)   a,b,c: (COUT, CIN, FL)   out: (B, COUT, TOUT, 4)

#define B_    2
#define CIN_  16
#define COUT_ 16
#define T_    2048
#define FL_   9
#define TOUT_ 2040
#define NQ    2        // co per thread (scalar, loop)

__device__ __forceinline__ float rcpf(float x) {
    float r; asm("rcp.approx.f32 %0,%1;" : "=f"(r) : "f"(x));
    return r;
}

__global__ __launch_bounds__(32 * CIN_)
void qconv1d_kernel(const float* __restrict__ x,
                    const float* __restrict__ pa,
                    const float* __restrict__ pb,
                    const float* __restrict__ pc,
                    float* __restrict__ out)
{
    __shared__ float4 sp[NQ][CIN_][FL_];        // {a,b,c,0} per (co,ci,f)
    __shared__ float4 red[CIN_ - 1][32][NQ];    // folded partials

    const int tx  = threadIdx.x;
    const int ci  = threadIdx.y;
    const int tid = ci * 32 + tx;
    const int t   = blockIdx.x * 32 + tx;
    const int co0 = blockIdx.y * NQ;
    const int b   = blockIdx.z;
    const int tL  = t < TOUT_ ? t : (TOUT_ - 1);

    // pack params into smem: 288 entries, 512 threads
    if (tid < NQ * CIN_ * FL_) {
        const int j   = tid / (CIN_ * FL_);
        const int rem = tid % (CIN_ * FL_);
        const int cci = rem / FL_;
        const int f   = rem % FL_;
        const int src = ((co0 + j) * CIN_ + cci) * FL_ + f;
        sp[j][cci][f] = make_float4(__ldg(pa + src), __ldg(pb + src), __ldg(pc + src), 0.f);
    }
    __syncthreads();

    const float4* xr = reinterpret_cast<const float4*>(x)
                     + ((size_t)b * CIN_ + ci) * T_ + tL;

    // center tap qp; pre-doubled copies
    const float4 v4 = __ldg(xr + 4);
    const float pw = v4.x, vx = v4.y, vy = v4.z, vz = v4.w;
    const float vdx = vx + vx, vdy = vy + vy, vdz = vz + vz;
    const float vsq  = vx * vx + vy * vy + vz * vz;
    const float nvsq = -vsq;

    // sign-split accumulators per co
    float aw[NQ], ax[NQ], ay[NQ], az[NQ];
    float Sn[NQ], nx[NQ], ny[NQ], nz[NQ];
    #pragma unroll
    for (int j = 0; j < NQ; ++j) {
        aw[j]=0.f; ax[j]=0.f; ay[j]=0.f; az[j]=0.f;
        Sn[j]=0.f; nx[j]=0.f; ny[j]=0.f; nz[j]=0.f;
    }

    #pragma unroll
    for (int f = 0; f < FL_; ++f) {
        const float4 u4 = __ldg(xr + f);
        const float s = u4.x, ux = u4.y, uy = u4.z, uz = u4.w;

        // co-invariants (pre-doubled): R(w) = w^2 u + w*cr + (dd v - vsq u)
        const float dd  = vdx*ux + vdy*uy + vdz*uz;            // 2 v.u
        const float crx = vdy*uz - vdz*uy;                     // 2 (v x u)
        const float cry = vdz*ux - vdx*uz;
        const float crz = vdx*uy - vdy*ux;
        const float a0x = fmaf(dd, vx, nvsq * ux);
        const float a0y = fmaf(dd, vy, nvsq * uy);
        const float a0z = fmaf(dd, vz, nvsq * uz);

        #pragma unroll
        for (int j = 0; j < NQ; ++j) {
            const float4 p = sp[j][ci][f];                     // {a,b,c}
            const float w   = pw + p.z;
            const float nsq = fmaf(w, w, vsq);
            const float rn  = rcpf(nsq);
            const float arn = p.x * rn;

            const float Rx = fmaf(w, fmaf(w, ux, crx), a0x) * arn;
            const float Ry = fmaf(w, fmaf(w, uy, cry), a0y) * arn;
            const float Rz = fmaf(w, fmaf(w, uz, crz), a0z) * arn;
            const float Rw = s * p.x;
            const float qw = s + p.y;

            // acc += (q + b e) (x) R, negatives collected separately
            aw[j] = fmaf(qw, Rw, aw[j]);
            Sn[j] = fmaf(ux, Rx, Sn[j]);
            Sn[j] = fmaf(uy, Ry, Sn[j]);
            Sn[j] = fmaf(uz, Rz, Sn[j]);
            ax[j] = fmaf(qw, Rx, ax[j]);
            ax[j] = fmaf(ux, Rw, ax[j]);
            ax[j] = fmaf(uy, Rz, ax[j]);
            nx[j] = fmaf(uz, Ry, nx[j]);
            ay[j] = fmaf(qw, Ry, ay[j]);
            ny[j] = fmaf(ux, Rz, ny[j]);
            ay[j] = fmaf(uy, Rw, ay[j]);
            ay[j] = fmaf(uz, Rx, ay[j]);
            az[j] = fmaf(qw, Rz, az[j]);
            az[j] = fmaf(ux, Ry, az[j]);
            nz[j] = fmaf(uy, Rx, nz[j]);
            az[j] = fmaf(uz, Rw, az[j]);
        }
    }

    // fold negatives once
    #pragma unroll
    for (int j = 0; j < NQ; ++j) {
        aw[j] -= Sn[j];
        ax[j] -= nx[j];
        ay[j] -= ny[j];
        az[j] -= nz[j];
    }

    // flat reduction over 16 ci warps
    if (ci > 0) {
        #pragma unroll
        for (int j = 0; j < NQ; ++j)
            red[ci - 1][tx][j] = make_float4(aw[j], ax[j], ay[j], az[j]);
    }
    __syncthreads();
    if (ci == 0 && t < TOUT_) {
        #pragma unroll
        for (int j = 0; j < NQ; ++j) {
            #pragma unroll
            for (int k = 0; k < CIN_ - 1; ++k) {
                const float4 r = red[k][tx][j];
                aw[j] += r.x; ax[j] += r.y; ay[j] += r.z; az[j] += r.w;
            }
            reinterpret_cast<float4*>(out)[((size_t)b * COUT_ + co0 + j) * TOUT_ + t]
                = make_float4(aw[j], ax[j], ay[j], az[j]);
        }
    }
}

extern "C" void kernel_launch(void* const* d_in, const int* in_sizes, int n_in,
                              void* d_out, int out_size)
{
    const float* x  = (const float*)d_in[0];
    const float* pa = (const float*)d_in[1];
    const float* pb = (const float*)d_in[2];
    const float* pc = (const float*)d_in[3];
    float* out = (float*)d_out;

    dim3 block(32, CIN_, 1);
    dim3 grid((TOUT_ + 31) / 32, COUT_ / NQ, B_);
    qconv1d_kernel<<<grid, block>>>(x, pa, pb, pc, out);
}

// round 17
// speedup vs baseline: 1.4332x; 1.2166x over previous
#include <cuda_runtime.h>

// QConv1d, conjugation closed form; f32x2 lanes hold the CO-PAIR (R13, verified best).
// Cuts: sign-split accumulators (no nR negations) + fused {a,b} LDS.128.
// x: (B, CIN, T, 4)   a,b,c: (COUT, CIN, FL)   out: (B, COUT, TOUT, 4)

#define B_    2
#define CIN_  16
#define COUT_ 16
#define T_    2048
#define FL_   9
#define TOUT_ 2040
#define NQ    2        // co per thread (packed in f32x2 halves)

typedef unsigned long long ull;

struct __align__(16) ull2x { ull a, b; };

__device__ __forceinline__ ull pk2(float lo, float hi) {
    ull r; asm("mov.b64 %0,{%1,%2};" : "=l"(r)
               : "r"(__float_as_uint(lo)), "r"(__float_as_uint(hi)));
    return r;
}
__device__ __forceinline__ void upk2(ull v, float& lo, float& hi) {
    unsigned a, b; asm("mov.b64 {%0,%1},%2;" : "=r"(a), "=r"(b) : "l"(v));
    lo = __uint_as_float(a); hi = __uint_as_float(b);
}
__device__ __forceinline__ ull bc2(float v) { return pk2(v, v); }
__device__ __forceinline__ ull f2(ull a, ull b, ull c) {
    ull r; asm("fma.rn.f32x2 %0,%1,%2,%3;" : "=l"(r) : "l"(a), "l"(b), "l"(c));
    return r;
}
__device__ __forceinline__ ull m2(ull a, ull b) {
    ull r; asm("mul.rn.f32x2 %0,%1,%2;" : "=l"(r) : "l"(a), "l"(b));
    return r;
}
__device__ __forceinline__ ull a2_(ull a, ull b) {
    ull r; asm("add.rn.f32x2 %0,%1,%2;" : "=l"(r) : "l"(a), "l"(b));
    return r;
}
__device__ __forceinline__ float rcpf(float x) {
    float r; asm("rcp.approx.f32 %0,%1;" : "=f"(r) : "f"(x));
    return r;
}

__global__ __launch_bounds__(32 * CIN_)
void qconv1d_kernel(const float* __restrict__ x,
                    const float* __restrict__ pa,
                    const float* __restrict__ pb,
                    const float* __restrict__ pc,
                    float* __restrict__ out)
{
    __shared__ ull2x spAB[CIN_][FL_];           // packed {a,b} over the co-pair
    __shared__ ull   spC[CIN_][FL_];            // packed {c}
    __shared__ ull   red[CIN_ - 1][32][4];

    const int tx  = threadIdx.x;
    const int ci  = threadIdx.y;
    const int tid = ci * 32 + tx;
    const int t   = blockIdx.x * 32 + tx;
    const int co0 = blockIdx.y * NQ;
    const int b   = blockIdx.z;
    const int tL  = t < TOUT_ ? t : (TOUT_ - 1);

    // pack params over the co-pair: 144 entries, 512 threads
    if (tid < CIN_ * FL_) {
        const int cci = tid / FL_, f = tid % FL_;
        const int s0 = (co0 * CIN_ + cci) * FL_ + f;
        const int s1 = s0 + CIN_ * FL_;
        ull2x ab;
        ab.a = pk2(__ldg(pa + s0), __ldg(pa + s1));
        ab.b = pk2(__ldg(pb + s0), __ldg(pb + s1));
        spAB[cci][f] = ab;
        spC[cci][f]  = pk2(__ldg(pc + s0), __ldg(pc + s1));
    }
    __syncthreads();

    const float4* xr = reinterpret_cast<const float4*>(x)
                     + ((size_t)b * CIN_ + ci) * T_ + tL;

    // center tap qp — scalar; one-time doubled copies
    const float4 v4 = __ldg(xr + 4);
    const float pw = v4.x, vx = v4.y, vy = v4.z, vz = v4.w;
    const float vdx = vx + vx, vdy = vy + vy, vdz = vz + vz;   // 2v
    const float vsq  = vx * vx + vy * vy + vz * vz;
    const float nvsq = -vsq;
    const ull pw2  = bc2(pw);
    const ull vsq2 = bc2(vsq);

    // positive accumulators + sign-split negative accumulators
    ull aw = 0, ax = 0, ay = 0, az = 0;
    ull Sn = 0, nx = 0, ny = 0, nz = 0;

    #pragma unroll
    for (int f = 0; f < FL_; ++f) {
        const float4 u4 = __ldg(xr + f);
        const float s = u4.x, ux = u4.y, uy = u4.z, uz = u4.w;

        // scalar co-invariants (pre-doubled): R(w) = w^2 u + w*cr + (dd v - vsq u)
        const float dd  = vdx*ux + vdy*uy + vdz*uz;            // 2 v.u
        const float crx = vdy*uz - vdz*uy;                     // 2 (v x u)
        const float cry = vdz*ux - vdx*uz;
        const float crz = vdx*uy - vdy*ux;
        const float a0x = fmaf(dd, vx, nvsq * ux);
        const float a0y = fmaf(dd, vy, nvsq * uy);
        const float a0z = fmaf(dd, vz, nvsq * uz);

        // broadcast to packed lanes (once per f, shared by both co)
        const ull s2   = bc2(s);
        const ull ux2  = bc2(ux);
        const ull uy2  = bc2(uy);
        const ull uz2  = bc2(uz);
        const ull crx2 = bc2(crx);
        const ull cry2 = bc2(cry);
        const ull crz2 = bc2(crz);
        const ull a0x2 = bc2(a0x);
        const ull a0y2 = bc2(a0y);
        const ull a0z2 = bc2(a0z);

        // packed per-co body (both co at once)
        const ull2x AB = spAB[ci][f];
        const ull C2 = spC[ci][f];

        const ull w2   = a2_(pw2, C2);
        const ull nsq2 = f2(w2, w2, vsq2);
        float nlo, nhi; upk2(nsq2, nlo, nhi);
        const ull rn2  = pk2(rcpf(nlo), rcpf(nhi));
        const ull arn2 = m2(AB.a, rn2);

        const ull Rx = m2(f2(w2, f2(w2, ux2, crx2), a0x2), arn2);
        const ull Ry = m2(f2(w2, f2(w2, uy2, cry2), a0y2), arn2);
        const ull Rz = m2(f2(w2, f2(w2, uz2, crz2), a0z2), arn2);
        const ull Rw = m2(s2, AB.a);
        const ull qw2 = a2_(s2, AB.b);

        // acc += (q + b e) (x) R  — negatives collected separately
        aw = f2(qw2, Rw, aw);
        Sn = f2(ux2, Rx, Sn);
        Sn = f2(uy2, Ry, Sn);
        Sn = f2(uz2, Rz, Sn);
        ax = f2(qw2, Rx, ax);
        ax = f2(ux2, Rw, ax);
        ax = f2(uy2, Rz, ax);
        nx = f2(uz2, Ry, nx);
        ay = f2(qw2, Ry, ay);
        ny = f2(ux2, Rz, ny);
        ay = f2(uy2, Rw, ay);
        ay = f2(uz2, Rx, ay);
        az = f2(qw2, Rz, az);
        az = f2(ux2, Ry, az);
        nz = f2(uy2, Rx, nz);
        az = f2(uz2, Rw, az);
    }

    // fold negatives once
    {
        const ull NEG1 = bc2(-1.0f);
        aw = f2(Sn, NEG1, aw);
        ax = f2(nx, NEG1, ax);
        ay = f2(ny, NEG1, ay);
        az = f2(nz, NEG1, az);
    }

    // flat reduction over 16 ci warps (packed adds)
    if (ci > 0) {
        red[ci - 1][tx][0] = aw;
        red[ci - 1][tx][1] = ax;
        red[ci - 1][tx][2] = ay;
        red[ci - 1][tx][3] = az;
    }
    __syncthreads();
    if (ci == 0 && t < TOUT_) {
        #pragma unroll
        for (int k = 0; k < CIN_ - 1; ++k) {
            aw = a2_(aw, red[k][tx][0]);
            ax = a2_(ax, red[k][tx][1]);
            ay = a2_(ay, red[k][tx][2]);
            az = a2_(az, red[k][tx][3]);
        }
        float w0, w1, x0, x1, y0, y1, z0, z1;
        upk2(aw, w0, w1); upk2(ax, x0, x1); upk2(ay, y0, y1); upk2(az, z0, z1);
        float4* o4 = reinterpret_cast<float4*>(out) + (size_t)b * COUT_ * TOUT_ + t;
        o4[(size_t)(co0 + 0) * TOUT_] = make_float4(w0, x0, y0, z0);
        o4[(size_t)(co0 + 1) * TOUT_] = make_float4(w1, x1, y1, z1);
    }
}

extern "C" void kernel_launch(void* const* d_in, const int* in_sizes, int n_in,
                              void* d_out, int out_size)
{
    const float* x  = (const float*)d_in[0];
    const float* pa = (const float*)d_in[1];
    const float* pb = (const float*)d_in[2];
    const float* pc = (const float*)d_in[3];
    float* out = (float*)d_out;

    dim3 block(32, CIN_, 1);
    dim3 grid((TOUT_ + 31) / 32, COUT_ / NQ, B_);
    qconv1d_kernel<<<grid, block>>>(x, pa, pb, pc, out);
}